// round 17
// baseline (speedup 1.0000x reference)
#include <cuda_runtime.h>
#include <cuda_bf16.h>
#include <math.h>

#define TSEQ 128
#define HU   64
#define NG   256
#define BATCH 2048

typedef unsigned long long u64;
typedef unsigned int u32;

// Pre-transposed split-bf16 weights (written by prep kernel, n-major [n][k])
__device__ __nv_bfloat16 g_w1t_hi[256 * 128], g_w1t_lo[256 * 128];
__device__ __nv_bfloat16 g_u1t_hi[256 * 64],  g_u1t_lo[256 * 64];
__device__ __nv_bfloat16 g_w2t_hi[256 * 64],  g_w2t_lo[256 * 64];
__device__ __nv_bfloat16 g_u2t_hi[256 * 64],  g_u2t_lo[256 * 64];

// ---------------------------------------------------------------------------
__device__ __forceinline__ float tanh_ap(float x) {
    float y; asm("tanh.approx.f32 %0, %1;" : "=f"(y) : "f"(x)); return y;
}
__device__ __forceinline__ float sig_ap(float x) {
    return fmaf(0.5f, tanh_ap(0.5f * x), 0.5f);
}
__device__ __forceinline__ u32 smem_u32(const void* p) {
    u32 a;
    asm("{ .reg .u64 t; cvta.to.shared.u64 t, %1; cvt.u32.u64 %0, t; }"
        : "=r"(a) : "l"(p));
    return a;
}
__device__ __forceinline__ void ldsm4(u32 r[4], u32 addr) {
    asm volatile("ldmatrix.sync.aligned.m8n8.x4.shared.b16 {%0,%1,%2,%3}, [%4];"
                 : "=r"(r[0]), "=r"(r[1]), "=r"(r[2]), "=r"(r[3]) : "r"(addr));
}
__device__ __forceinline__ void ldsm2(u32 r[2], u32 addr) {
    asm volatile("ldmatrix.sync.aligned.m8n8.x2.shared.b16 {%0,%1}, [%2];"
                 : "=r"(r[0]), "=r"(r[1]) : "r"(addr));
}
__device__ __forceinline__ void mma16816(float d[4], const u32 a[4], const u32 b[2]) {
    asm volatile(
        "mma.sync.aligned.m16n8k16.row.col.f32.bf16.bf16.f32 "
        "{%0,%1,%2,%3}, {%4,%5,%6,%7}, {%8,%9}, {%0,%1,%2,%3};"
        : "+f"(d[0]), "+f"(d[1]), "+f"(d[2]), "+f"(d[3])
        : "r"(a[0]), "r"(a[1]), "r"(a[2]), "r"(a[3]), "r"(b[0]), "r"(b[1]));
}
__device__ __forceinline__ u32 cvt2bf(float lo, float hi) {
    u32 r; asm("cvt.rn.bf16x2.f32 %0, %1, %2;" : "=r"(r) : "f"(hi), "f"(lo));
    return r;
}

// ---------------------------------------------------------------------------
// Prep: transpose + split all four weight matrices to n-major bf16 hi/lo.
// grid (256), block (128): n = blockIdx.x, k = threadIdx.x
// ---------------------------------------------------------------------------
__global__ void prep_kernel(const float* __restrict__ W1, const float* __restrict__ U1,
                            const float* __restrict__ W2, const float* __restrict__ U2)
{
    int n = blockIdx.x, k = threadIdx.x;
    {
        float v = W1[(size_t)k * NG + n];
        __nv_bfloat16 h = __float2bfloat16(v);
        g_w1t_hi[n * 128 + k] = h;
        g_w1t_lo[n * 128 + k] = __float2bfloat16(v - __bfloat162float(h));
    }
    if (k < 64) {
        float v = U1[(size_t)k * NG + n];
        __nv_bfloat16 h = __float2bfloat16(v);
        g_u1t_hi[n * 64 + k] = h;
        g_u1t_lo[n * 64 + k] = __float2bfloat16(v - __bfloat162float(h));
        v = W2[(size_t)k * NG + n];
        h = __float2bfloat16(v);
        g_w2t_hi[n * 64 + k] = h;
        g_w2t_lo[n * 64 + k] = __float2bfloat16(v - __bfloat162float(h));
        v = U2[(size_t)k * NG + n];
        h = __float2bfloat16(v);
        g_u2t_hi[n * 64 + k] = h;
        g_u2t_lo[n * 64 + k] = __float2bfloat16(v - __bfloat162float(h));
    }
}

// ---------------------------------------------------------------------------
// Interleaved two-layer LSTM megakernel.
// Per combined step t: L1 computes h1(t) (if t<T), L2 computes h2(t-1)
// (if t>0). Both layers' MMAs are issued in the same barrier window and
// share the h1(t-1) A-fragments. h1 lives ONLY in smem.
// 128 blocks x 16 batch rows, 256 threads (8 warps); warp w owns n-cols
// {8w..8w+7}+64g for both layers. 2 barriers/step.
// ---------------------------------------------------------------------------
#define SW1H 0
#define SW1L 69632
#define SW2H 139264
#define SW2L 176128
#define SH1  212992          // h1 hi 2304 | lo 2304
#define SH2  217600          // h2 hi 2304 | lo 2304
#define SXH  222208          // x hi 4352 | lo 4352
#define SXL  226560
#define MEGA_SMEM 230912

__global__ __launch_bounds__(256, 1) void lstm_mega(
    const float* __restrict__ Xf,
    const float* __restrict__ b1, const float* __restrict__ b2,
    float* __restrict__ outf)
{
    extern __shared__ char smem[];
    const u32 sb = smem_u32(smem);
    const int tid = threadIdx.x;
    const int w   = tid >> 5;
    const int l   = tid & 31;
    const int b0  = blockIdx.x * 16;

    const u32 bnrow = (u32)(8 * w + (l & 7));          // b-frag n row base (+64g)
    const u32 bkoff = (u32)(((l >> 3) & 1) * 16);      // b-frag k-half byte off
    const u32 arow  = (u32)((l & 7) + ((l >> 3) & 1) * 8);
    const u32 aoffh = arow * 144 + (u32)(l >> 4) * 16; // h A-frag (pitch 144)
    const u32 aoffx = arow * 272 + (u32)(l >> 4) * 16; // x A-frag (pitch 272)

    // ---- stage U1T into SW1 region, preload U1 b-frags ----
#pragma unroll
    for (int i = 0; i < 8; i++) {
        int idx = tid + i * 256;              // 2048 uint4
        int n = idx >> 3, q = idx & 7;
        *(uint4*)(smem + n * 144 + q * 16)         = ((const uint4*)g_u1t_hi)[idx];
        *(uint4*)(smem + 36864 + n * 144 + q * 16) = ((const uint4*)g_u1t_lo)[idx];
    }
    __syncthreads();
    u32 u1h[4][4][2], u1l[4][4][2];
#pragma unroll
    for (int g = 0; g < 4; g++)
#pragma unroll
        for (int ks = 0; ks < 4; ks++) {
            u32 off = (u32)(64 * g) * 144 + bnrow * 144 + bkoff + ks * 32;
            ldsm2(u1h[g][ks], sb + off);
            ldsm2(u1l[g][ks], sb + 36864 + off);
        }
    __syncthreads();

    // ---- stage U2T, preload U2 b-frags ----
#pragma unroll
    for (int i = 0; i < 8; i++) {
        int idx = tid + i * 256;
        int n = idx >> 3, q = idx & 7;
        *(uint4*)(smem + n * 144 + q * 16)         = ((const uint4*)g_u2t_hi)[idx];
        *(uint4*)(smem + 36864 + n * 144 + q * 16) = ((const uint4*)g_u2t_lo)[idx];
    }
    __syncthreads();
    u32 u2h[4][4][2], u2l[4][4][2];
#pragma unroll
    for (int g = 0; g < 4; g++)
#pragma unroll
        for (int ks = 0; ks < 4; ks++) {
            u32 off = (u32)(64 * g) * 144 + bnrow * 144 + bkoff + ks * 32;
            ldsm2(u2h[g][ks], sb + off);
            ldsm2(u2l[g][ks], sb + 36864 + off);
        }
    __syncthreads();

    // ---- stage W1 (pitch 272) and W2 (pitch 144), zero h bufs ----
#pragma unroll
    for (int i = 0; i < 16; i++) {
        int idx = tid + i * 256;              // 4096 uint4
        int n = idx >> 4, q = idx & 15;
        *(uint4*)(smem + SW1H + n * 272 + q * 16) = ((const uint4*)g_w1t_hi)[idx];
        *(uint4*)(smem + SW1L + n * 272 + q * 16) = ((const uint4*)g_w1t_lo)[idx];
    }
#pragma unroll
    for (int i = 0; i < 8; i++) {
        int idx = tid + i * 256;              // 2048 uint4
        int n = idx >> 3, q = idx & 7;
        *(uint4*)(smem + SW2H + n * 144 + q * 16) = ((const uint4*)g_w2t_hi)[idx];
        *(uint4*)(smem + SW2L + n * 144 + q * 16) = ((const uint4*)g_w2t_lo)[idx];
    }
#pragma unroll
    for (int i = 0; i < 9; i++)
        *(u32*)(smem + SH1 + (u32)(tid + i * 256) * 4) = 0;   // 9216 B = h1+h2

    // ---- stage x(0) ----
    const int srow = tid >> 4, sq = tid & 15;
#define STAGE_X(tt)                                                           \
    {                                                                         \
        const float* s = Xf + ((size_t)(b0 + srow) * TSEQ + (tt)) * 128 + sq * 8; \
        float4 v0 = *(const float4*)s;                                        \
        float4 v1 = *(const float4*)(s + 4);                                  \
        __nv_bfloat16 a0 = __float2bfloat16(v0.x), a1 = __float2bfloat16(v0.y); \
        __nv_bfloat16 a2 = __float2bfloat16(v0.z), a3 = __float2bfloat16(v0.w); \
        __nv_bfloat16 a4 = __float2bfloat16(v1.x), a5 = __float2bfloat16(v1.y); \
        __nv_bfloat16 a6 = __float2bfloat16(v1.z), a7 = __float2bfloat16(v1.w); \
        uint4 hi4, lo4;                                                       \
        hi4.x = ((u32)__bfloat16_as_ushort(a1) << 16) | __bfloat16_as_ushort(a0); \
        hi4.y = ((u32)__bfloat16_as_ushort(a3) << 16) | __bfloat16_as_ushort(a2); \
        hi4.z = ((u32)__bfloat16_as_ushort(a5) << 16) | __bfloat16_as_ushort(a4); \
        hi4.w = ((u32)__bfloat16_as_ushort(a7) << 16) | __bfloat16_as_ushort(a6); \
        lo4.x = cvt2bf(v0.x - __bfloat162float(a0), v0.y - __bfloat162float(a1)); \
        lo4.y = cvt2bf(v0.z - __bfloat162float(a2), v0.w - __bfloat162float(a3)); \
        lo4.z = cvt2bf(v1.x - __bfloat162float(a4), v1.y - __bfloat162float(a5)); \
        lo4.w = cvt2bf(v1.z - __bfloat162float(a6), v1.w - __bfloat162float(a7)); \
        *(uint4*)(smem + SXH + srow * 272 + sq * 16) = hi4;                   \
        *(uint4*)(smem + SXL + srow * 272 + sq * 16) = lo4;                   \
    }
    STAGE_X(0)

    // ---- bias seeds + per-thread ownership ----
    const int r   = l >> 2;
    const int cq2 = 2 * (l & 3);
    const int u0  = 8 * w + cq2;
    float bs1[8], bs2[8];
#pragma unroll
    for (int g = 0; g < 4; g++) {
        bs1[g * 2 + 0] = b1[64 * g + u0];
        bs1[g * 2 + 1] = b1[64 * g + u0 + 1];
        bs2[g * 2 + 0] = b2[64 * g + u0];
        bs2[g * 2 + 1] = b2[64 * g + u0 + 1];
    }
    float c1[4] = {0.f, 0.f, 0.f, 0.f};
    float c2[4] = {0.f, 0.f, 0.f, 0.f};
    __syncthreads();

    // ================= main loop (129 iterations) ==========================
    for (int t = 0; t <= TSEQ; t++) {
        const bool doL1 = (t < TSEQ);
        const bool doL2 = (t > 0);

        float a1h[16], a1lo[16], a2h[16], a2lo[16];
#pragma unroll
        for (int i = 0; i < 16; i++) {
            a1h[i] = bs1[(i >> 2) * 2 + (i & 1)];  a1lo[i] = 0.f;
            a2h[i] = bs2[(i >> 2) * 2 + (i & 1)];  a2lo[i] = 0.f;
        }

        // --- shared h1(t-1) A-frags: U1*h1 (L1) and W2*h1 (L2) ---
#pragma unroll
        for (int ks = 0; ks < 4; ks++) {
            u32 hh_[4], hl_[4];
            ldsm4(hh_, sb + SH1 + aoffh + ks * 32);
            ldsm4(hl_, sb + SH1 + 2304 + aoffh + ks * 32);
            if (doL1) {
#pragma unroll
                for (int g = 0; g < 4; g++) {
                    mma16816(&a1h[g * 4],  hh_, u1h[g][ks]);
                    mma16816(&a1lo[g * 4], hl_, u1h[g][ks]);
                    mma16816(&a1lo[g * 4], hh_, u1l[g][ks]);
                }
            }
            if (doL2) {
#pragma unroll
                for (int g = 0; g < 4; g++) {
                    u32 wh_[2], wl_[2];
                    u32 off = (u32)(64 * g) * 144 + bnrow * 144 + bkoff + ks * 32;
                    ldsm2(wh_, sb + SW2H + off);
                    ldsm2(wl_, sb + SW2L + off);
                    mma16816(&a2h[g * 4],  hh_, wh_);
                    mma16816(&a2lo[g * 4], hl_, wh_);
                    mma16816(&a2lo[g * 4], hh_, wl_);
                }
            }
        }

        // --- U2 * h2(t-2) ---
        if (doL2) {
#pragma unroll
            for (int ks = 0; ks < 4; ks++) {
                u32 hh_[4], hl_[4];
                ldsm4(hh_, sb + SH2 + aoffh + ks * 32);
                ldsm4(hl_, sb + SH2 + 2304 + aoffh + ks * 32);
#pragma unroll
                for (int g = 0; g < 4; g++) {
                    mma16816(&a2h[g * 4],  hh_, u2h[g][ks]);
                    mma16816(&a2lo[g * 4], hl_, u2h[g][ks]);
                    mma16816(&a2lo[g * 4], hh_, u2l[g][ks]);
                }
            }
        }

        // --- x(t) @ W1 ---
        if (doL1) {
#pragma unroll
            for (int ks = 0; ks < 8; ks++) {
                u32 xh_[4], xl_[4];
                ldsm4(xh_, sb + SXH + aoffx + ks * 32);
                ldsm4(xl_, sb + SXL + aoffx + ks * 32);
#pragma unroll
                for (int g = 0; g < 4; g++) {
                    u32 wh_[2], wl_[2];
                    u32 off = (u32)(64 * g) * 272 + bnrow * 272 + bkoff + ks * 32;
                    ldsm2(wh_, sb + SW1H + off);
                    ldsm2(wl_, sb + SW1L + off);
                    mma16816(&a1h[g * 4],  xh_, wh_);
                    mma16816(&a1lo[g * 4], xl_, wh_);
                    mma16816(&a1lo[g * 4], xh_, wl_);
                }
            }
        }

        __syncthreads();   // MID: all ldsm of h1/h2/x(t) done before overwrite

        // --- L1 epilogue -> h1(t) (smem only) ---
        if (doL1) {
#pragma unroll
            for (int r01 = 0; r01 < 2; r01++) {
                float hv[2];
#pragma unroll
                for (int e = 0; e < 2; e++) {
                    int fi = r01 * 2 + e;
                    float zi = a1h[0 * 4 + fi] + a1lo[0 * 4 + fi];
                    float zf = a1h[1 * 4 + fi] + a1lo[1 * 4 + fi];
                    float zg = a1h[2 * 4 + fi] + a1lo[2 * 4 + fi];
                    float zo = a1h[3 * 4 + fi] + a1lo[3 * 4 + fi];
                    float ig = sig_ap(zi), fg = sig_ap(zf);
                    float gg = tanh_ap(zg), og = sig_ap(zo);
                    int ci = r01 * 2 + e;
                    c1[ci] = fmaf(fg, c1[ci], ig * gg);
                    hv[e] = og * tanh_ap(c1[ci]);
                }
                __nv_bfloat16 q0 = __float2bfloat16(hv[0]);
                __nv_bfloat16 q1 = __float2bfloat16(hv[1]);
                u32 hip = ((u32)__bfloat16_as_ushort(q1) << 16) | __bfloat16_as_ushort(q0);
                u32 lop = cvt2bf(hv[0] - __bfloat162float(q0),
                                 hv[1] - __bfloat162float(q1));
                int row_s = r + 8 * r01;
                u32 hoff = (u32)(row_s * 144 + u0 * 2);
                *(u32*)(smem + SH1 + hoff)        = hip;
                *(u32*)(smem + SH1 + 2304 + hoff) = lop;
            }
            if (t + 1 < TSEQ) STAGE_X(t + 1)
        }

        // --- L2 epilogue -> h2(t-1) + global output ---
        if (doL2) {
#pragma unroll
            for (int r01 = 0; r01 < 2; r01++) {
                float hv[2];
#pragma unroll
                for (int e = 0; e < 2; e++) {
                    int fi = r01 * 2 + e;
                    float zi = a2h[0 * 4 + fi] + a2lo[0 * 4 + fi];
                    float zf = a2h[1 * 4 + fi] + a2lo[1 * 4 + fi];
                    float zg = a2h[2 * 4 + fi] + a2lo[2 * 4 + fi];
                    float zo = a2h[3 * 4 + fi] + a2lo[3 * 4 + fi];
                    float ig = sig_ap(zi), fg = sig_ap(zf);
                    float gg = sig_ap(zg), og = sig_ap(zo);
                    int ci = r01 * 2 + e;
                    c2[ci] = fmaf(fg, c2[ci], ig * gg);
                    hv[e] = og * sig_ap(c2[ci]);
                }
                __nv_bfloat16 q0 = __float2bfloat16(hv[0]);
                __nv_bfloat16 q1 = __float2bfloat16(hv[1]);
                u32 hip = ((u32)__bfloat16_as_ushort(q1) << 16) | __bfloat16_as_ushort(q0);
                u32 lop = cvt2bf(hv[0] - __bfloat162float(q0),
                                 hv[1] - __bfloat162float(q1));
                int row_s = r + 8 * r01;
                u32 hoff = (u32)(row_s * 144 + u0 * 2);
                *(u32*)(smem + SH2 + hoff)        = hip;
                *(u32*)(smem + SH2 + 2304 + hoff) = lop;
                *(float2*)(outf + ((size_t)(b0 + row_s) * TSEQ + (t - 1)) * HU + u0) =
                    make_float2(hv[0], hv[1]);
            }
        }
        __syncthreads();   // END
    }
#undef STAGE_X
}

// ---------------------------------------------------------------------------
extern "C" void kernel_launch(void* const* d_in, const int* in_sizes, int n_in,
                              void* d_out, int out_size)
{
    const float* x  = (const float*)d_in[0];
    const float* W1 = (const float*)d_in[1];
    const float* U1 = (const float*)d_in[2];
    const float* b1 = (const float*)d_in[3];
    const float* W2 = (const float*)d_in[4];
    const float* U2 = (const float*)d_in[5];
    const float* b2 = (const float*)d_in[6];
    float* out = (float*)d_out;

    cudaFuncSetAttribute(lstm_mega,
                         cudaFuncAttributeMaxDynamicSharedMemorySize, MEGA_SMEM);

    prep_kernel<<<256, 128>>>(W1, U1, W2, U2);
    lstm_mega<<<BATCH / 16, 256, MEGA_SMEM>>>(x, b1, b2, out);
}